// round 5
// baseline (speedup 1.0000x reference)
#include <cuda_runtime.h>

#define HW     65536
#define BATCH  64
#define NTB    128
#define NK     100
#define SHIFT  19
#define NB2    8192          // 2^13 coarse bins on top 13 key bits
#define CAP    4096
#define SCAP   1024          // per-slice candidate cap
#define KEEP   1024
#define KSAMP  64
#define SLICES 4
#define TPB_A  512
#define TPB_B  512
#define D2R    0.017453292519943295f

__device__ unsigned long long g_cand[NTB][SLICES][SCAP];
__device__ unsigned           g_scnt[NTB][SLICES];
__device__ float2             g_thr[NTB];           // x=float thresh, y=bitcast(b0)
__device__ float              g_xy[2][BATCH][NK][2];
__device__ float              g_part[BATCH][2];
__device__ unsigned           g_done = 0;

// order-preserving float->uint key (ascending)
__device__ __forceinline__ unsigned fkey(float f) {
    unsigned u = __float_as_uint(f);
    return u ^ ((unsigned)((int)u >> 31) | 0x80000000u);
}
__device__ __forceinline__ float inv_fkey(unsigned k) {
    unsigned u = (k & 0x80000000u) ? (k ^ 0x80000000u) : ~k;
    return __uint_as_float(u);
}

// Find bin b with (count in bins > b) < K <= (count in bins >= b). Block-collective.
template <int T>
__device__ void suffix_find(const unsigned* hist, int NB, unsigned K,
                            unsigned* s_ws, unsigned* s_bin, unsigned* s_above) {
    int tid  = threadIdx.x;
    int lane = tid & 31, warp = tid >> 5;
    int bpt  = (NB + T - 1) / T;
    int base = tid * bpt;
    unsigned p = 0;
    for (int j = 0; j < bpt; j++) {
        int b = base + j;
        if (b < NB) p += hist[b];
    }
    unsigned v = p;
    for (int d = 1; d < 32; d <<= 1) {
        unsigned o = __shfl_down_sync(0xffffffffu, v, d);
        if (lane + d < 32) v += o;
    }
    if (lane == 0) s_ws[warp] = v;
    __syncthreads();
    unsigned add = 0;
    for (int w = warp + 1; w < T / 32; w++) add += s_ws[w];
    unsigned sAfter = (v - p) + add;
    if (sAfter < K && sAfter + p >= K) {
        unsigned cum = sAfter;
        for (int j = bpt - 1; j >= 0; j--) {
            int b = base + j;
            if (b >= NB) continue;
            unsigned h = hist[b];
            if (cum + h >= K) { *s_bin = (unsigned)b; *s_above = cum; break; }
            cum += h;
        }
    }
    __syncthreads();
}

__device__ __forceinline__ const float* tb_base(const float* hm_p, const float* hm_t, int tb) {
    return (tb >= BATCH) ? hm_t + (size_t)(tb - BATCH) * HW
                         : hm_p + (size_t)tb * HW;
}

// ---------------- Kernel A: sample threshold + sliced collect ----------------
__global__ void __launch_bounds__(TPB_A, 4)
topk_collect(const float* __restrict__ hm_p, const float* __restrict__ hm_t) {
    __shared__ __align__(16) unsigned sh_hist[NB2];   // 32KB
    __shared__ unsigned s_ws[TPB_A / 32];
    __shared__ unsigned s_bin, s_above, s_cnt;

    int tid   = threadIdx.x;
    int tb    = blockIdx.x >> 2;
    int slice = blockIdx.x & 3;
    const float4* src4 = (const float4*)tb_base(hm_p, hm_t, tb);

    // ---- sampled threshold: same 4096 points in every slice-block ----
    for (int i = tid; i < NB2; i += TPB_A) sh_hist[i] = 0;
    __syncthreads();
#pragma unroll
    for (int s = 0; s < 2; s++) {
        float4 f = src4[(tid + s * TPB_A) * 16];
        atomicAdd(&sh_hist[fkey(f.x) >> SHIFT], 1u);
        atomicAdd(&sh_hist[fkey(f.y) >> SHIFT], 1u);
        atomicAdd(&sh_hist[fkey(f.z) >> SHIFT], 1u);
        atomicAdd(&sh_hist[fkey(f.w) >> SHIFT], 1u);
    }
    __syncthreads();
    suffix_find<TPB_A>(sh_hist, NB2, KSAMP, s_ws, &s_bin, &s_above);
    unsigned b0 = s_bin;
    float thresh = inv_fkey(b0 << SHIFT);
    if (slice == 0 && tid == 0)
        g_thr[tb] = make_float2(thresh, __uint_as_float(b0));

    // ---- collect this slice into its private global segment ----
    if (tid == 0) s_cnt = 0;
    __syncthreads();
    unsigned long long* seg = g_cand[tb][slice];
    const float4* s4 = src4 + slice * (HW / 4 / SLICES);
#pragma unroll
    for (int j = 0; j < HW / 4 / SLICES / TPB_A; j++) {   // 8 iters
        int i4 = tid + j * TPB_A;
        float4 f = s4[i4];
        float v[4] = {f.x, f.y, f.z, f.w};
#pragma unroll
        for (int c = 0; c < 4; c++) {
            if (v[c] >= thresh) {
                unsigned pos = atomicAdd(&s_cnt, 1u);
                if (pos < SCAP) {
                    unsigned idx = (unsigned)((slice * (HW / 4 / SLICES) + i4) * 4 + c);
                    seg[pos] = ((unsigned long long)fkey(v[c]) << 16) |
                               (unsigned long long)(65535u - idx);
                }
            }
        }
    }
    __syncthreads();
    if (tid == 0) g_scnt[tb][slice] = s_cnt;
}

// ---------------- Kernel B: merge + refine + sort (with exact fallback) -----
__global__ void __launch_bounds__(TPB_B)
refine_sort(const float* __restrict__ hm_p, const float* __restrict__ hm_t) {
    __shared__ __align__(16) unsigned sh_hist[NB2];            // 32KB; aliased by cand
    unsigned long long* cand = (unsigned long long*)sh_hist;   // 4096 entries
    __shared__ __align__(16) unsigned long long sk[KEEP];      // 8KB
    __shared__ unsigned rh[256];
    __shared__ unsigned s_ws[TPB_B / 32];
    __shared__ unsigned s_bin, s_above, s_cnt, s_kcnt;

    int tid = threadIdx.x;
    int tb  = blockIdx.x;
    const float4* src4 = (const float4*)tb_base(hm_p, hm_t, tb);

    unsigned c0 = g_scnt[tb][0], c1 = g_scnt[tb][1];
    unsigned c2 = g_scnt[tb][2], c3 = g_scnt[tb][3];
    unsigned total = c0 + c1 + c2 + c3;
    bool bad = (c0 > SCAP) || (c1 > SCAP) || (c2 > SCAP) || (c3 > SCAP) ||
               (total < NK) || (total > CAP);
    unsigned b0;
    unsigned Mc;

    if (!bad) {
        b0 = __float_as_uint(g_thr[tb].y);
        unsigned off[4] = {0, c0, c0 + c1, c0 + c1 + c2};
        unsigned cc[4]  = {c0, c1, c2, c3};
#pragma unroll
        for (int s = 0; s < 4; s++)
            for (unsigned i = tid; i < cc[s]; i += TPB_B)
                cand[off[s] + i] = g_cand[tb][s][i];
        Mc = total;
        __syncthreads();
    } else {
        // exact path: full histogram + in-smem collect
        for (int i = tid; i < NB2; i += TPB_B) sh_hist[i] = 0;
        __syncthreads();
        for (int j = 0; j < HW / 4 / TPB_B; j++) {    // 32 iters
            float4 f = src4[tid + j * TPB_B];
            atomicAdd(&sh_hist[fkey(f.x) >> SHIFT], 1u);
            atomicAdd(&sh_hist[fkey(f.y) >> SHIFT], 1u);
            atomicAdd(&sh_hist[fkey(f.z) >> SHIFT], 1u);
            atomicAdd(&sh_hist[fkey(f.w) >> SHIFT], 1u);
        }
        __syncthreads();
        suffix_find<TPB_B>(sh_hist, NB2, NK, s_ws, &s_bin, &s_above);
        b0 = s_bin;
        float thresh = inv_fkey(b0 << SHIFT);
        if (tid == 0) s_cnt = 0;
        __syncthreads();
        for (int j = 0; j < HW / 4 / TPB_B; j++) {
            int i4 = tid + j * TPB_B;
            float4 f = src4[i4];
            float v[4] = {f.x, f.y, f.z, f.w};
#pragma unroll
            for (int c = 0; c < 4; c++) {
                if (v[c] >= thresh) {
                    unsigned pos = atomicAdd(&s_cnt, 1u);
                    if (pos < CAP) {
                        unsigned idx = (unsigned)(i4 * 4 + c);
                        cand[pos] = ((unsigned long long)fkey(v[c]) << 16) |
                                    (unsigned long long)(65535u - idx);
                    }
                }
            }
        }
        __syncthreads();
        Mc = s_cnt;
        if (Mc > CAP) Mc = CAP;
    }

    // ---- refine to ~NK using next 8 key bits (clamped offset from b0) ----
    if (tid < 256) rh[tid] = 0;
    if (tid == 0) s_kcnt = 0;
    __syncthreads();
    unsigned b0base = b0 << 8;
    for (unsigned i = tid; i < Mc; i += TPB_B) {
        unsigned key = (unsigned)(cand[i] >> 16);
        unsigned off = (key >> (SHIFT - 8)) - b0base;
        if (off > 255u) off = 255u;
        atomicAdd(&rh[off], 1u);
    }
    __syncthreads();
    suffix_find<TPB_B>(rh, 256, NK, s_ws, &s_bin, &s_above);
    unsigned r0 = s_bin;
    for (unsigned i = tid; i < Mc; i += TPB_B) {
        unsigned long long e = cand[i];
        unsigned key = (unsigned)(e >> 16);
        unsigned off = (key >> (SHIFT - 8)) - b0base;
        if (off > 255u) off = 255u;
        if (off >= r0) {
            unsigned p = atomicAdd(&s_kcnt, 1u);
            if (p < KEEP) sk[p] = e;
        }
    }
    __syncthreads();
    unsigned Mk = s_kcnt;
    bool big = (Mk > KEEP);     // pathological tie storm: sort full cand buffer
    unsigned long long* buf = big ? cand : sk;
    unsigned n = big ? Mc : Mk;

    // ---- exact bitonic sort: desc on (key, 65535-idx) => jax tie order ----
    unsigned P2 = 128;
    while (P2 < n) P2 <<= 1;
    for (unsigned i = n + tid; i < P2; i += TPB_B) buf[i] = 0ULL;
    __syncthreads();
    for (unsigned k = 2; k <= P2; k <<= 1) {
        for (unsigned j = k >> 1; j > 0; j >>= 1) {
            for (unsigned i = tid; i < P2; i += TPB_B) {
                unsigned ixj = i ^ j;
                if (ixj > i) {
                    unsigned long long a = buf[i], b = buf[ixj];
                    bool up = (i & k) == 0;
                    if (up ? (a < b) : (a > b)) { buf[i] = b; buf[ixj] = a; }
                }
            }
            __syncthreads();
        }
    }

    if (tid < NK) {
        unsigned idx = 65535u - (unsigned)(buf[tid] & 0xFFFFULL);
        int tensor = (tb >= BATCH) ? 1 : 0;
        g_xy[tensor][tb & 63][tid][0] = (float)(idx & 255u);   // x
        g_xy[tensor][tb & 63][tid][1] = (float)(idx >> 8);     // y
    }
}

// ---------------- Loss + fused finalize (last-block pattern) ----------------
__device__ __forceinline__ float gwd_one(float xp, float yp, float wp, float hp, float ap,
                                         float xt, float yt, float wt, float ht, float at) {
    wp = fminf(fmaxf(wp, 1e-7f), 1e7f);
    hp = fminf(fmaxf(hp, 1e-7f), 1e7f);
    wt = fminf(fmaxf(wt, 1e-7f), 1e7f);
    ht = fminf(fmaxf(ht, 1e-7f), 1e7f);
    float sp, cp, st, ct;
    sincosf(ap * D2R, &sp, &cp);
    sincosf(at * D2R, &st, &ct);
    float s1p = 0.5f * wp, s2p = 0.5f * hp, s1t = 0.5f * wt, s2t = 0.5f * ht;
    float dx = xp - xt, dy = yp - yt;
    float xyd = dx * dx + dy * dy;
    float q1p = s1p * s1p, q2p = s2p * s2p, q1t = s1t * s1t, q2t = s2t * s2t;
    float Ap = cp * cp * q1p + sp * sp * q2p;
    float Bp = cp * sp * (q1p - q2p);
    float Cp = sp * sp * q1p + cp * cp * q2p;
    float At = ct * ct * q1t + st * st * q2t;
    float Bt = ct * st * (q1t - q2t);
    float Ct = st * st * q1t + ct * ct * q2t;
    float whr  = q1p + q2p + q1t + q2t;
    float tr   = Ap * At + 2.f * Bp * Bt + Cp * Ct;
    float dets = s1p * s2p * s1t * s2t;
    whr -= 2.f * sqrtf(fmaxf(tr + 2.f * dets, 0.f));
    float d = fmaxf(xyd + whr, 0.f);
    d = log1pf(d);
    return 1.f - 1.f / (1.f + d);
}

__global__ void __launch_bounds__(128)
loss_kernel(const float* __restrict__ ab_p, const float* __restrict__ ang_p,
            const float* __restrict__ ab_t, const float* __restrict__ ang_t,
            const int* __restrict__ ind, const int* __restrict__ msk,
            float* __restrict__ out) {
    int b = blockIdx.x, t = threadIdx.x;
    float loss = 0.f, mval = 0.f;
    if (t < NK) {
        int r   = b * NK + t;
        float m = (float)msk[r];
        int id  = ind[r];
        size_t ab_base = (size_t)b * (2 * HW);
        float wp = ab_p[ab_base + id] * 2.f * m;
        float hp = ab_p[ab_base + HW + id] * 2.f * m;
        float ap = (ang_p[(size_t)b * HW + id] - 90.f) * m;
        float xp = g_xy[0][b][t][0] * m, yp = g_xy[0][b][t][1] * m;
        float xt = g_xy[1][b][t][0] * m, yt = g_xy[1][b][t][1] * m;
        float wt = ab_t[r * 2] * 2.f * m, ht = ab_t[r * 2 + 1] * 2.f * m;
        float at = (ang_t[r] - 90.f) * m;
        loss = gwd_one(xp, yp, wp, hp, ap, xt, yt, wt, ht, at);
        mval = m;
    }
    for (int d = 16; d > 0; d >>= 1) {
        loss += __shfl_down_sync(0xffffffffu, loss, d);
        mval += __shfl_down_sync(0xffffffffu, mval, d);
    }
    __shared__ float rl[4], rm[4];
    __shared__ unsigned s_last;
    if ((t & 31) == 0) { rl[t >> 5] = loss; rm[t >> 5] = mval; }
    __syncthreads();
    if (t == 0) {
        g_part[b][0] = rl[0] + rl[1] + rl[2] + rl[3];
        g_part[b][1] = rm[0] + rm[1] + rm[2] + rm[3];
        __threadfence();
        s_last = (atomicAdd(&g_done, 1u) == BATCH - 1);
    }
    __syncthreads();
    if (s_last) {
        __threadfence();                 // acquire: make all g_part visible
        float l = 0.f, m = 0.f;
        if (t < BATCH) { l = g_part[t][0]; m = g_part[t][1]; }
        for (int d = 16; d > 0; d >>= 1) {
            l += __shfl_down_sync(0xffffffffu, l, d);
            m += __shfl_down_sync(0xffffffffu, m, d);
        }
        if ((t & 31) == 0) { rl[t >> 5] = l; rm[t >> 5] = m; }
        __syncthreads();
        if (t == 0) {
            out[0] = (rl[0] + rl[1]) / ((rm[0] + rm[1]) + 1e-8f);
            g_done = 0;                  // reset for next graph replay
        }
    }
}

extern "C" void kernel_launch(void* const* d_in, const int* in_sizes, int n_in,
                              void* d_out, int out_size) {
    const float* hm_p  = (const float*)d_in[0];
    const float* ab_p  = (const float*)d_in[1];
    const float* ang_p = (const float*)d_in[2];
    const float* hm_t  = (const float*)d_in[3];
    const float* ab_t  = (const float*)d_in[4];
    const float* ang_t = (const float*)d_in[5];
    const int*   ind   = (const int*)d_in[6];
    const int*   msk   = (const int*)d_in[7];
    float*       out   = (float*)d_out;

    topk_collect<<<NTB * SLICES, TPB_A>>>(hm_p, hm_t);
    refine_sort<<<NTB, TPB_B>>>(hm_p, hm_t);
    loss_kernel<<<BATCH, 128>>>(ab_p, ang_p, ab_t, ang_t, ind, msk, out);
}